// round 12
// baseline (speedup 1.0000x reference)
#include <cuda_runtime.h>
#include <cstdint>

// Depthwise 3D conv 3x3x3, SAME, stride 1.
// x: (4,16,112,112,64) f32 NDHWC ; w: (3,3,3,1,64) f32
//
// R11: d-rolling + float2 lanes. One warp owns a 2(H) x 4(W) spatial tile
// for ALL 16 output depths and streams the 16 input D-slices exactly once;
// three rolling accumulator sets receive each slice via the matching kd
// weight plane. L1 amplification 3x (vs 7.7x for kd-re-reading kernels).
// All 27 weight float2 in regs; ~126 regs -> 16 warps/SM. Branch-free
// predicated halo loads (lesson of R9/R10).

typedef unsigned long long u64;

#define W_DIM   112
#define H_DIM   112
#define D_DIM   16
#define N_DIM   4
#define C2      32                    // float2 channel groups = warp lanes
#define WS      4
#define HS      2
#define WSEG    (W_DIM / WS)          // 28
#define HT2     (H_DIM / HS)          // 56
#define WPB     4
#define TPB     (WPB * 32)            // 128

#define ROW_F2    (W_DIM * C2)                 // 3584 u64 per H-row
#define SLICE_F2  ((size_t)H_DIM * W_DIM * C2) // u64 per D-slice
#define IMG_F2    ((size_t)D_DIM * SLICE_F2)   // u64 per batch n

__device__ __forceinline__ void fma2(u64& d, u64 a, u64 b) {
    asm("fma.rn.f32x2 %0, %1, %2, %0;" : "+l"(d) : "l"(a), "l"(b));
}

// One input slice s: 4 halo rows, each loaded 6-wide (predicated) then
// applied to the rolling acc sets. NXT=d=s+1 (kd=0), CUR=d=s (kd=1),
// PRV=d=s-1 (kd=2). After the slice, PRV is complete -> store + reset.
#define DO_SLICE(S_EXPR, I_CUR, I_NXT, I_PRV, DO_PRV, DO_STORE)            \
    {                                                                      \
        const int s = (S_EXPR);                                            \
        const u64* xs = xbase + (size_t)s * SLICE_F2;                      \
        _Pragma("unroll")                                                  \
        for (int r = 0; r < HS + 2; r++) {                                 \
            const bool hv = (r == 0) ? htop : (r == HS + 1) ? hbot : true; \
            const u64* p = xs + r * ROW_F2;                                \
            u64 rb[WS + 2];                                                \
            rb[0] = (hv && lv) ? p[0] : 0ull;                              \
            _Pragma("unroll")                                              \
            for (int j = 1; j <= WS; j++)                                  \
                rb[j] = hv ? p[j * C2] : 0ull;                             \
            rb[WS + 1] = (hv && rv) ? p[(WS + 1) * C2] : 0ull;             \
            _Pragma("unroll")                                              \
            for (int oh = 0; oh < HS; oh++) {                              \
                const int k = r - oh;   /* kh tap for this output row */   \
                if (k >= 0 && k < 3) {                                     \
                    _Pragma("unroll")                                      \
                    for (int ow = 0; ow < WS; ow++) {                      \
                        _Pragma("unroll")                                  \
                        for (int kw = 0; kw < 3; kw++) {                   \
                            fma2(acc[I_NXT][oh][ow], rb[ow + kw],          \
                                 wgt[0][k][kw]);                           \
                            fma2(acc[I_CUR][oh][ow], rb[ow + kw],          \
                                 wgt[1][k][kw]);                           \
                            if (DO_PRV)                                    \
                                fma2(acc[I_PRV][oh][ow], rb[ow + kw],      \
                                     wgt[2][k][kw]);                       \
                        }                                                  \
                    }                                                      \
                }                                                          \
            }                                                              \
        }                                                                  \
        if (DO_STORE) {                                                    \
            u64* o = ob + (size_t)(s - 1) * SLICE_F2;                      \
            _Pragma("unroll")                                              \
            for (int i = 0; i < HS; i++)                                   \
                _Pragma("unroll")                                          \
                for (int j = 0; j < WS; j++) {                             \
                    o[(i * W_DIM + j) * C2] = acc[I_PRV][i][j];            \
                    acc[I_PRV][i][j] = 0ull;                               \
                }                                                          \
        }                                                                  \
    }

__global__ void __launch_bounds__(TPB, 4)
dwconv3d_kernel(const u64* __restrict__ xin,
                const u64* __restrict__ win,
                u64* __restrict__ out)
{
    const int lane = threadIdx.x & 31;
    const int gw   = blockIdx.x * WPB + (threadIdx.x >> 5);

    const int wseg = gw % WSEG;                // 28
    int t          = gw / WSEG;
    const int hp   = t % HT2;                  // 56
    const int n    = t / HT2;                  // 4

    const int h0 = hp * HS;
    const int w0 = wseg * WS;
    const bool lv   = (wseg != 0);
    const bool rv   = (wseg != WSEG - 1);
    const bool htop = (hp != 0);
    const bool hbot = (hp != HT2 - 1);

    // all 27 weight float2 in registers
    const u64* wb = win + lane;
    u64 wgt[3][3][3];
    #pragma unroll
    for (int kd = 0; kd < 3; kd++)
        #pragma unroll
        for (int kh = 0; kh < 3; kh++)
            #pragma unroll
            for (int kw = 0; kw < 3; kw++)
                wgt[kd][kh][kw] = wb[((kd * 3 + kh) * 3 + kw) * C2];

    // input base at (n, d=0, h0-1, w0-1, lane)
    const u64* xbase = xin + (size_t)n * IMG_F2
                     + ((ptrdiff_t)(h0 - 1) * W_DIM + (w0 - 1)) * C2 + lane;
    // output base at (n, d=0, h0, w0, lane)
    u64* ob = out + (size_t)n * IMG_F2
            + ((size_t)h0 * W_DIM + w0) * C2 + lane;

    u64 acc[3][HS][WS];
    #pragma unroll
    for (int q = 0; q < 3; q++)
        #pragma unroll
        for (int i = 0; i < HS; i++)
            #pragma unroll
            for (int j = 0; j < WS; j++)
                acc[q][i][j] = 0ull;

    // s=0: cur=acc[0] (d=0), nxt=acc[1] (d=1); no prev, no store.
    DO_SLICE(0, 0, 1, 2, false, false)

    // s = 1..15: 5 iterations x 3 slices so the rolling index is compile-time.
    #pragma unroll 1
    for (int tt = 0; tt < 5; tt++) {
        const int sb = 1 + 3 * tt;
        DO_SLICE(sb + 0, 1, 2, 0, true, true)   // s%3==1
        DO_SLICE(sb + 1, 2, 0, 1, true, true)   // s%3==2
        DO_SLICE(sb + 2, 0, 1, 2, true, true)   // s%3==0
    }

    // d=15 = CUR at s=15 = acc[0]
    {
        u64* o = ob + (size_t)15 * SLICE_F2;
        #pragma unroll
        for (int i = 0; i < HS; i++)
            #pragma unroll
            for (int j = 0; j < WS; j++)
                o[(i * W_DIM + j) * C2] = acc[0][i][j];
    }
}

extern "C" void kernel_launch(void* const* d_in, const int* in_sizes, int n_in,
                              void* d_out, int out_size) {
    const u64* x = (const u64*)d_in[0];
    const u64* w = (const u64*)d_in[1];
    u64* o = (u64*)d_out;

    // warps = N * HT2 * WSEG = 4*56*28 = 6272 ; blocks = 1568
    const int total_warps = N_DIM * HT2 * WSEG;
    dwconv3d_kernel<<<total_warps / WPB, TPB>>>(x, w, o);
}

// round 15
// speedup vs baseline: 1.0441x; 1.0441x over previous
#include <cuda_runtime.h>
#include <cstdint>

// Depthwise 3D conv 3x3x3, SAME, stride 1.
// x: (4,16,112,112,64) f32 NDHWC ; w: (3,3,3,1,64) f32
//
// R12: champion tile (4H x 7W, float2 lanes, kd-outer) with R5's BRANCH-FREE
// predicated body (no intra-plane branches -> ptxas batches loads wide, high
// MLP). Fewest issues/output of any config + best batching. 20 warps/SM via
// __launch_bounds__(128,5).

typedef unsigned long long u64;

#define W_DIM   112
#define H_DIM   112
#define D_DIM   16
#define N_DIM   4
#define C2      32                  // float2 channel groups = warp lanes
#define WS      7
#define HS      4
#define WSEG    (W_DIM / WS)        // 16
#define HT4     (H_DIM / HS)        // 28
#define WPB     4                   // warps per block
#define TPB     (WPB * 32)          // 128

#define ROW_F2    (W_DIM * C2)                 // u64 per H-row (3584)
#define SLICE_F2  ((size_t)H_DIM * W_DIM * C2) // u64 per D-slice
#define IMG_F2    ((size_t)D_DIM * SLICE_F2)   // u64 per batch n

__device__ __forceinline__ void fma2(u64& d, u64 a, u64 b) {
    asm("fma.rn.f32x2 %0, %1, %2, %0;" : "+l"(d) : "l"(a), "l"(b));
}

__global__ void __launch_bounds__(TPB, 5)
dwconv3d_kernel(const u64* __restrict__ xin,
                const u64* __restrict__ win,
                u64* __restrict__ out)
{
    const int lane = threadIdx.x & 31;
    const int gw   = blockIdx.x * WPB + (threadIdx.x >> 5);

    const int wseg = gw & (WSEG - 1);          // 16
    int t          = gw >> 4;
    const int ht   = t % HT4;                  // 28
    t             /= HT4;
    const int d    = t & (D_DIM - 1);          // 16
    const int n    = t >> 4;                   // 4

    const int h0 = ht * HS;
    const int w0 = wseg * WS;
    const bool lv   = (wseg != 0);
    const bool rv   = (wseg != WSEG - 1);
    const bool htop = (ht != 0);
    const bool hbot = (ht != HT4 - 1);

    const u64* wb = win + lane;
    // base at (n, d=0, h0-1, w0-1, lane); row/col offsets are compile-time
    // immediates off the per-kd slice pointer.
    const u64* xb = xin + (size_t)n * IMG_F2
                  + ((ptrdiff_t)(h0 - 1) * W_DIM + (w0 - 1)) * C2 + lane;

    u64 acc[HS][WS];
    #pragma unroll
    for (int i = 0; i < HS; i++)
        #pragma unroll
        for (int j = 0; j < WS; j++)
            acc[i][j] = 0ull;

    #pragma unroll
    for (int kd = 0; kd < 3; kd++) {
        const int id = d + kd - 1;
        if (id < 0 || id >= D_DIM) continue;   // warp-uniform, kd-granular only

        u64 wgt[3][3];
        #pragma unroll
        for (int kh = 0; kh < 3; kh++)
            #pragma unroll
            for (int kw = 0; kw < 3; kw++)
                wgt[kh][kw] = wb[((kd * 3 + kh) * 3 + kw) * C2];

        const u64* xs = xb + (size_t)id * SLICE_F2;

        // BRANCH-FREE plane: all 6 rows processed, edge rows predicated to
        // zero via SELs so ptxas can batch loads across the whole plane.
        #pragma unroll
        for (int r = 0; r < HS + 2; r++) {
            const bool hv = (r == 0) ? htop : (r == HS + 1) ? hbot : true;
            const u64* p = xs + r * ROW_F2;    // immediate-folded offsets

            u64 row[WS + 2];
            row[0] = (hv && lv) ? p[0] : 0ull;
            #pragma unroll
            for (int j = 1; j <= WS; j++)
                row[j] = hv ? p[j * C2] : 0ull;
            row[WS + 1] = (hv && rv) ? p[(WS + 1) * C2] : 0ull;

            #pragma unroll
            for (int oh = 0; oh < HS; oh++) {
                // input row ih = h0 + r - 1 feeds output oh with tap k = r - oh
                const int k = r - oh;
                if (k >= 0 && k < 3) {
                    #pragma unroll
                    for (int ow = 0; ow < WS; ow++)
                        #pragma unroll
                        for (int kw = 0; kw < 3; kw++)
                            fma2(acc[oh][ow], row[ow + kw], wgt[k][kw]);
                }
            }
        }
    }

    u64* o = out + (size_t)n * IMG_F2 + (size_t)d * SLICE_F2
           + ((size_t)h0 * W_DIM + w0) * C2 + lane;
    #pragma unroll
    for (int i = 0; i < HS; i++)
        #pragma unroll
        for (int j = 0; j < WS; j++)
            o[(i * W_DIM + j) * C2] = acc[i][j];
}

extern "C" void kernel_launch(void* const* d_in, const int* in_sizes, int n_in,
                              void* d_out, int out_size) {
    const u64* x = (const u64*)d_in[0];
    const u64* w = (const u64*)d_in[1];
    u64* o = (u64*)d_out;

    // total warps = N * D * HT4 * WSEG = 4*16*28*16 = 28672
    const int total_warps = N_DIM * D_DIM * HT4 * WSEG;
    dwconv3d_kernel<<<total_warps / WPB, TPB>>>(x, w, o);
}